// round 1
// baseline (speedup 1.0000x reference)
#include <cuda_runtime.h>

#define NB 32
#define NA 5
#define NC 80
#define NH 76
#define NW 76
#define HW (NH*NW)            // 5776
#define MAXT 50
#define NCELL (NB*NA*HW)      // 924160
#define CHS (NA*(5+NC))       // 425

__constant__ float c_aw[5] = {1.3221f, 3.19275f, 5.05587f, 9.47112f, 11.2364f};
__constant__ float c_ah[5] = {1.73145f, 4.00944f, 8.09892f, 4.84053f, 10.0071f};

// scratch (static device globals — no allocation)
__device__ unsigned char g_over[NCELL];   // cur_iou > 0.6 flag
__device__ int           g_match[NCELL];  // winning target index (last-write-wins == max t), -1 = none
#define TR 12
// per (b,t): [0]gx [1]gy [2]gw [3]gh [4]tx [5]ty [6]tw [7]th [8]tconf [9](int)tcls [10](int)valid
__device__ float  g_trec[NB*MAXT*TR];
__device__ double g_acc;

__device__ __forceinline__ float sigm(float v) {
    return __fdividef(1.f, 1.f + __expf(-v));
}

// ---------------------------------------------------------------- init
__global__ void k_init() {
    int i = blockIdx.x * blockDim.x + threadIdx.x;
    if (i < NCELL) { g_over[i] = 0; g_match[i] = -1; }
    if (i == 0) g_acc = 0.0;
}

// ---------------------------------------------------------------- per-target prep
// One block per batch b, thread t handles target t.
__global__ void k_prep(const float* __restrict__ out, const float* __restrict__ tgt) {
    int b = blockIdx.x;
    int t = threadIdx.x;
    __shared__ unsigned char ok[MAXT];
    if (t < MAXT) {
        float cx = tgt[b*MAXT*5 + t*5 + 1];
        ok[t] = (cx != 0.f) ? 1 : 0;
    }
    __syncthreads();
    if (t >= MAXT) return;

    int valid = 1;
    for (int u = 0; u <= t; u++) valid &= (int)ok[u];   // cumprod semantics

    const float* tp = tgt + b*MAXT*5 + t*5;
    float cls = tp[0];
    float gx = tp[1]*NW, gy = tp[2]*NH, gw = tp[3]*NW, gh = tp[4]*NH;

    // best anchor by shape IoU (first index wins ties, strict >)
    float best = -1.f; int bn = 0;
    #pragma unroll
    for (int a = 0; a < NA; a++) {
        float aw = c_aw[a], ah = c_ah[a];
        float inter = fminf(gw, aw) * fminf(gh, ah);
        float uni   = gw*gh + aw*ah - inter;
        float iou   = __fdividef(inter, uni);
        if (iou > best) { best = iou; bn = a; }
    }

    int gi = (int)gx; gi = max(0, min(NW-1, gi));
    int gj = (int)gy; gj = max(0, min(NH-1, gj));

    // matched pred box (gather 4 values)
    int base = (b*CHS + bn*(5+NC))*HW + gj*NW + gi;
    float o0 = out[base], o1 = out[base+HW], o2 = out[base+2*HW], o3 = out[base+3*HW];
    float mpx = sigm(o0) + (float)gi;
    float mpy = sigm(o1) + (float)gj;
    float mpw = __expf(o2) * c_aw[bn];
    float mph = __expf(o3) * c_ah[bn];

    // t_iou = IoU(gt_box, matched_pred)
    float mx = fminf(gx - 0.5f*gw, mpx - 0.5f*mpw);
    float Mx = fmaxf(gx + 0.5f*gw, mpx + 0.5f*mpw);
    float my = fminf(gy - 0.5f*gh, mpy - 0.5f*mph);
    float My = fmaxf(gy + 0.5f*gh, mpy + 0.5f*mph);
    float cw = gw + mpw - (Mx - mx);
    float ch = gh + mph - (My - my);
    float inter = (cw <= 0.f || ch <= 0.f) ? 0.f : cw*ch;
    float uni   = gw*gh + mpw*mph - inter;
    float t_iou = __fdividef(inter, uni);

    float* r = g_trec + (b*MAXT + t)*TR;
    r[0] = gx; r[1] = gy; r[2] = gw; r[3] = gh;
    r[4] = gx - (float)gi;
    r[5] = gy - (float)gj;
    r[6] = __logf(__fdividef(gw, c_aw[bn]));
    r[7] = __logf(__fdividef(gh, c_ah[bn]));
    r[8] = t_iou;
    ((int*)r)[9]  = (int)cls;
    ((int*)r)[10] = valid;

    if (valid) {
        int cell = ((b*NA + bn)*NH + gj)*NW + gi;
        atomicMax(&g_match[cell], t);   // max t == last sequential write wins
    }
}

// ---------------------------------------------------------------- rasterize IoU>0.6 windows
// One block per (b,t). Necessary condition for IoU>0.6: |px-gx| <= 0.4*gw (per axis),
// px in (i, i+1)  =>  i in (gx-0.4gw-1, gx+0.4gw). +/-1 cell safety margin.
__global__ void k_raster(const float* __restrict__ out) {
    int b = blockIdx.x / MAXT;
    int t = blockIdx.x % MAXT;
    const float* r = g_trec + (b*MAXT + t)*TR;
    if (((const int*)r)[10] == 0) return;

    float gx = r[0], gy = r[1], gw = r[2], gh = r[3];
    float gx0 = gx - 0.5f*gw, gx1 = gx + 0.5f*gw;
    float gy0 = gy - 0.5f*gh, gy1 = gy + 0.5f*gh;
    float g375 = 0.375f * gw * gh;

    int i0 = max(0,    (int)floorf(gx - 0.4f*gw) - 1);
    int i1 = min(NW-1, (int)floorf(gx + 0.4f*gw) + 1);
    int j0 = max(0,    (int)floorf(gy - 0.4f*gh) - 1);
    int j1 = min(NH-1, (int)floorf(gy + 0.4f*gh) + 1);
    int wi = i1 - i0 + 1, wj = j1 - j0 + 1;
    int win = wi * wj;
    int tot = win * NA;

    for (int k = threadIdx.x; k < tot; k += blockDim.x) {
        int a  = k / win;
        int rr = k - a*win;
        int jq = rr / wi;
        int j  = j0 + jq;
        int i  = i0 + rr - jq*wi;
        int base = (b*CHS + a*(5+NC))*HW + j*NW + i;
        float o0 = out[base], o1 = out[base+HW], o2 = out[base+2*HW], o3 = out[base+3*HW];
        float px = sigm(o0) + (float)i;
        float py = sigm(o1) + (float)j;
        float pw = __expf(o2) * c_aw[a];
        float ph = __expf(o3) * c_ah[a];
        float cw = pw + gw - (fmaxf(px + 0.5f*pw, gx1) - fminf(px - 0.5f*pw, gx0));
        float ch = ph + gh - (fmaxf(py + 0.5f*ph, gy1) - fminf(py - 0.5f*ph, gy0));
        if (cw > 0.f && ch > 0.f) {
            float inter = cw * ch;
            // iou > 0.6  <=>  inter > 0.375*(parea+garea)
            if (inter > 0.375f*pw*ph + g375) {
                int cell = ((b*NA + a)*NH + j)*NW + i;
                g_over[cell] = 1;
            }
        }
    }
}

// ---------------------------------------------------------------- final pass over all cells
__global__ void k_final(const float* __restrict__ out) {
    int idx = blockIdx.x * blockDim.x + threadIdx.x;
    float contrib = 0.f;
    if (idx < NCELL) {
        int b   = idx / (NA*HW);
        int rem = idx - b*NA*HW;
        int a   = rem / HW;
        int hw  = rem - a*HW;
        int obase = (b*CHS + a*(5+NC))*HW + hw;
        float conf = sigm(out[obase + 4*HW]);
        int m = g_match[idx];
        if (m >= 0) {
            const float* r = g_trec + (b*MAXT + m)*TR;
            float o0 = out[obase], o1 = out[obase+HW];
            float o2 = out[obase+2*HW], o3 = out[obase+3*HW];
            float x = sigm(o0), y = sigm(o1);
            float dx = x - r[4], dy = y - r[5];
            float dw = o2 - r[6], dh = o3 - r[7];
            float dc = conf - r[8];
            contrib = 0.5f*(dx*dx + dy*dy + dw*dw + dh*dh) + 2.5f*dc*dc;
            // class cross-entropy (log-softmax over 80 strided logits)
            const float* lg = out + obase + 5*HW;
            float mx = -1e30f;
            for (int c = 0; c < NC; c++) mx = fmaxf(mx, lg[c*HW]);
            float s = 0.f;
            for (int c = 0; c < NC; c++) s += __expf(lg[c*HW] - mx);
            int tc = ((const int*)r)[9];
            contrib += mx + __logf(s) - lg[tc*HW];
        } else {
            float cm = g_over[idx] ? 0.f : 0.5f;   // NOOBJ_SCALE = 1
            contrib = cm * conf * conf;
        }
    }
    // block reduction -> double atomic
    unsigned mask = 0xFFFFFFFFu;
    float v = contrib;
    #pragma unroll
    for (int off = 16; off > 0; off >>= 1) v += __shfl_down_sync(mask, v, off);
    __shared__ float sw[8];
    int lane = threadIdx.x & 31, wid = threadIdx.x >> 5;
    if (lane == 0) sw[wid] = v;
    __syncthreads();
    if (wid == 0) {
        v = (lane < (int)(blockDim.x >> 5)) ? sw[lane] : 0.f;
        #pragma unroll
        for (int off = 4; off > 0; off >>= 1) v += __shfl_down_sync(mask, v, off);
        if (lane == 0) atomicAdd(&g_acc, (double)v);
    }
}

__global__ void k_finish(float* res) {
    res[0] = (float)g_acc;
}

// ---------------------------------------------------------------- launch
extern "C" void kernel_launch(void* const* d_in, const int* in_sizes, int n_in,
                              void* d_out, int out_size) {
    const float* out = (const float*)d_in[0];   // (32, 425, 76, 76)
    const float* tgt = (const float*)d_in[1];   // (32, 250)
    float* res = (float*)d_out;

    k_init  <<<(NCELL + 255)/256, 256>>>();
    k_prep  <<<NB, 64>>>(out, tgt);
    k_raster<<<NB*MAXT, 256>>>(out);
    k_final <<<(NCELL + 255)/256, 256>>>(out);
    k_finish<<<1, 1>>>(res);
}

// round 2
// speedup vs baseline: 1.1739x; 1.1739x over previous
#include <cuda_runtime.h>

#define NB 32
#define NA 5
#define NC 80
#define NH 76
#define NW 76
#define HW (NH*NW)            // 5776
#define MAXT 50
#define NCELL (NB*NA*HW)      // 924160
#define CHS (NA*(5+NC))       // 425

__constant__ float c_aw[5] = {1.3221f, 3.19275f, 5.05587f, 9.47112f, 11.2364f};
__constant__ float c_ah[5] = {1.73145f, 4.00944f, 8.09892f, 4.84053f, 10.0071f};

// scratch (static device globals — no allocation)
// flag per cell: 1 => no no-object contribution (either IoU>thresh or matched cell)
__device__ unsigned char g_flag[NCELL];
#define TR 16
// per (b,t): [0]gx [1]gy [2]gw [3]gh [4]tx [5]ty [6]tw [7]th [8]tconf
//            (int)[9]tcls (int)[10]valid (int)[11]winner (int)[12]obase
__device__ float  g_trec[NB*MAXT*TR];
__device__ double g_acc;

__device__ __forceinline__ float sigm(float v) {
    return __fdividef(1.f, 1.f + __expf(-v));
}

// ---------------------------------------------------------------- init (clear flags + acc)
__global__ void k_init() {
    int i = blockIdx.x * blockDim.x + threadIdx.x;
    if (i < NCELL/16) ((uint4*)g_flag)[i] = make_uint4(0,0,0,0);
    if (i == 0) g_acc = 0.0;
}

// ---------------------------------------------------------------- per-target prep
// One block per batch b, thread t handles target t. Shared dedup for winners.
__global__ void k_prep(const float* __restrict__ out, const float* __restrict__ tgt) {
    int b = blockIdx.x;
    int t = threadIdx.x;
    __shared__ unsigned char ok[MAXT];
    __shared__ int s_cell[MAXT];
    __shared__ int s_val[MAXT];
    if (t < MAXT) {
        float cx = tgt[b*MAXT*5 + t*5 + 1];
        ok[t] = (cx != 0.f) ? 1 : 0;
    }
    __syncthreads();
    if (t >= MAXT) return;

    int valid = 1;
    for (int u = 0; u <= t; u++) valid &= (int)ok[u];   // cumprod semantics

    const float* tp = tgt + b*MAXT*5 + t*5;
    float cls = tp[0];
    float gx = tp[1]*NW, gy = tp[2]*NH, gw = tp[3]*NW, gh = tp[4]*NH;

    // best anchor by shape IoU (first index wins ties, strict >)
    float best = -1.f; int bn = 0;
    #pragma unroll
    for (int a = 0; a < NA; a++) {
        float aw = c_aw[a], ah = c_ah[a];
        float inter = fminf(gw, aw) * fminf(gh, ah);
        float uni   = gw*gh + aw*ah - inter;
        float iou   = __fdividef(inter, uni);
        if (iou > best) { best = iou; bn = a; }
    }

    int gi = (int)gx; gi = max(0, min(NW-1, gi));
    int gj = (int)gy; gj = max(0, min(NH-1, gj));

    int cellIdx = ((b*NA + bn)*NH + gj)*NW + gi;           // flag-array index
    int obase   = (b*CHS + bn*(5+NC))*HW + gj*NW + gi;     // output-tensor offset

    s_cell[t] = cellIdx;
    s_val[t]  = valid;
    __syncthreads();

    // winner = valid and no later valid target hits the same cell (last-write-wins)
    int winner = valid;
    for (int u = t+1; u < MAXT; u++)
        if (s_val[u] && s_cell[u] == s_cell[t]) { winner = 0; break; }

    // matched pred box (gather 4 values)
    float o0 = out[obase], o1 = out[obase+HW], o2 = out[obase+2*HW], o3 = out[obase+3*HW];
    float mpx = sigm(o0) + (float)gi;
    float mpy = sigm(o1) + (float)gj;
    float mpw = __expf(o2) * c_aw[bn];
    float mph = __expf(o3) * c_ah[bn];

    // t_iou = IoU(gt_box, matched_pred)
    float mx = fminf(gx - 0.5f*gw, mpx - 0.5f*mpw);
    float Mx = fmaxf(gx + 0.5f*gw, mpx + 0.5f*mpw);
    float my = fminf(gy - 0.5f*gh, mpy - 0.5f*mph);
    float My = fmaxf(gy + 0.5f*gh, mpy + 0.5f*mph);
    float cw = gw + mpw - (Mx - mx);
    float ch = gh + mph - (My - my);
    float inter = (cw <= 0.f || ch <= 0.f) ? 0.f : cw*ch;
    float uni   = gw*gh + mpw*mph - inter;
    float t_iou = __fdividef(inter, uni);

    float* r = g_trec + (b*MAXT + t)*TR;
    r[0] = gx; r[1] = gy; r[2] = gw; r[3] = gh;
    r[4] = gx - (float)gi;
    r[5] = gy - (float)gj;
    r[6] = __logf(__fdividef(gw, c_aw[bn]));
    r[7] = __logf(__fdividef(gh, c_ah[bn]));
    r[8] = t_iou;
    ((int*)r)[9]  = (int)cls;
    ((int*)r)[10] = valid;
    ((int*)r)[11] = winner;
    ((int*)r)[12] = obase;

    if (winner) g_flag[cellIdx] = 1;   // matched cell: no no-object loss here
}

// ---------------------------------------------------------------- rasterize IoU>0.6 windows
// One block per (b,t). Necessary condition for IoU>0.6: |px-gx| <= 0.4*gw (per axis).
__global__ void k_raster(const float* __restrict__ out) {
    int b = blockIdx.x / MAXT;
    int t = blockIdx.x % MAXT;
    const float* r = g_trec + (b*MAXT + t)*TR;
    if (((const int*)r)[10] == 0) return;   // needs valid, not winner

    float gx = r[0], gy = r[1], gw = r[2], gh = r[3];
    float gx0 = gx - 0.5f*gw, gx1 = gx + 0.5f*gw;
    float gy0 = gy - 0.5f*gh, gy1 = gy + 0.5f*gh;
    float g375 = 0.375f * gw * gh;

    int i0 = max(0,    (int)floorf(gx - 0.4f*gw) - 1);
    int i1 = min(NW-1, (int)floorf(gx + 0.4f*gw) + 1);
    int j0 = max(0,    (int)floorf(gy - 0.4f*gh) - 1);
    int j1 = min(NH-1, (int)floorf(gy + 0.4f*gh) + 1);
    int wi = i1 - i0 + 1, wj = j1 - j0 + 1;
    int win = wi * wj;
    int tot = win * NA;

    for (int k = threadIdx.x; k < tot; k += blockDim.x) {
        int a  = k / win;
        int rr = k - a*win;
        int jq = rr / wi;
        int j  = j0 + jq;
        int i  = i0 + rr - jq*wi;
        int base = (b*CHS + a*(5+NC))*HW + j*NW + i;
        float o0 = __ldg(out+base), o1 = __ldg(out+base+HW);
        float o2 = __ldg(out+base+2*HW), o3 = __ldg(out+base+3*HW);
        float px = sigm(o0) + (float)i;
        float py = sigm(o1) + (float)j;
        float pw = __expf(o2) * c_aw[a];
        float ph = __expf(o3) * c_ah[a];
        float cw = pw + gw - (fmaxf(px + 0.5f*pw, gx1) - fminf(px - 0.5f*pw, gx0));
        float ch = ph + gh - (fmaxf(py + 0.5f*ph, gy1) - fminf(py - 0.5f*ph, gy0));
        if (cw > 0.f && ch > 0.f) {
            float inter = cw * ch;
            // iou > 0.6  <=>  inter > 0.375*(parea+garea)
            if (inter > 0.375f*pw*ph + g375) {
                g_flag[((b*NA + a)*NH + j)*NW + i] = 1;
            }
        }
    }
}

// ---------------------------------------------------------------- no-object conf loss (streaming)
// Each thread: 4 consecutive cells (never crosses an (b,a) plane since HW%4==0).
__global__ void k_noobj(const float* __restrict__ out) {
    int g = blockIdx.x * blockDim.x + threadIdx.x;
    int idx4 = g * 4;
    float contrib = 0.f;
    if (idx4 < NCELL) {
        int p  = idx4 / HW;            // 0..159  (b*5+a)
        int hw = idx4 - p * HW;
        int b  = p / NA, a = p - b*NA;
        const float* cptr = out + ((size_t)(b*CHS + a*(5+NC) + 4))*HW + hw;
        float4 c4 = *(const float4*)cptr;
        unsigned f4 = *(const unsigned*)(g_flag + idx4);
        float s0 = sigm(c4.x), s1 = sigm(c4.y), s2 = sigm(c4.z), s3 = sigm(c4.w);
        if (!(f4 & 0x000000FFu)) contrib += s0*s0;
        if (!(f4 & 0x0000FF00u)) contrib += s1*s1;
        if (!(f4 & 0x00FF0000u)) contrib += s2*s2;
        if (!(f4 & 0xFF000000u)) contrib += s3*s3;
        contrib *= 0.5f;   // NOOBJ_SCALE=1, loss = 0.5*sum(conf^2)
    }
    // block reduction -> double atomic
    unsigned mask = 0xFFFFFFFFu;
    float v = contrib;
    #pragma unroll
    for (int off = 16; off > 0; off >>= 1) v += __shfl_down_sync(mask, v, off);
    __shared__ float sw[8];
    int lane = threadIdx.x & 31, wid = threadIdx.x >> 5;
    if (lane == 0) sw[wid] = v;
    __syncthreads();
    if (wid == 0) {
        v = (lane < (int)(blockDim.x >> 5)) ? sw[lane] : 0.f;
        #pragma unroll
        for (int off = 4; off > 0; off >>= 1) v += __shfl_down_sync(mask, v, off);
        if (lane == 0) atomicAdd(&g_acc, (double)v);
    }
}

// ---------------------------------------------------------------- matched-cell loss
// One 96-thread block per winning target: cooperative 80-wide log-softmax.
__global__ void k_matched(const float* __restrict__ out) {
    int b = blockIdx.x / MAXT;
    int t = blockIdx.x % MAXT;
    const float* r = g_trec + (b*MAXT + t)*TR;
    if (((const int*)r)[11] == 0) return;   // winner only
    int obase = ((const int*)r)[12];

    int c = threadIdx.x;
    int lane = c & 31, wid = c >> 5;
    const float* lg = out + obase + 5*HW;
    float v = (c < NC) ? __ldg(lg + c*HW) : -1e30f;

    __shared__ float sm[3], ss[3];
    unsigned mask = 0xFFFFFFFFu;
    float m = v;
    #pragma unroll
    for (int off = 16; off > 0; off >>= 1) m = fmaxf(m, __shfl_xor_sync(mask, m, off));
    if (lane == 0) sm[wid] = m;
    __syncthreads();
    float mx = fmaxf(sm[0], fmaxf(sm[1], sm[2]));

    float e = (c < NC) ? __expf(v - mx) : 0.f;
    #pragma unroll
    for (int off = 16; off > 0; off >>= 1) e += __shfl_xor_sync(mask, e, off);
    if (lane == 0) ss[wid] = e;
    __syncthreads();

    if (c == 0) {
        float s = ss[0] + ss[1] + ss[2];
        int tc = ((const int*)r)[9];
        float ce = mx + __logf(s) - __ldg(lg + tc*HW);

        float o0 = out[obase], o1 = out[obase+HW];
        float o2 = out[obase+2*HW], o3 = out[obase+3*HW];
        float conf = sigm(out[obase+4*HW]);
        float dx = sigm(o0) - r[4];
        float dy = sigm(o1) - r[5];
        float dw = o2 - r[6];
        float dh = o3 - r[7];
        float dc = conf - r[8];
        float contrib = 0.5f*(dx*dx + dy*dy + dw*dw + dh*dh) + 2.5f*dc*dc + ce;
        atomicAdd(&g_acc, (double)contrib);
    }
}

__global__ void k_finish(float* res) {
    res[0] = (float)g_acc;
}

// ---------------------------------------------------------------- launch
extern "C" void kernel_launch(void* const* d_in, const int* in_sizes, int n_in,
                              void* d_out, int out_size) {
    const float* out = (const float*)d_in[0];   // (32, 425, 76, 76)
    const float* tgt = (const float*)d_in[1];   // (32, 250)
    float* res = (float*)d_out;

    k_init   <<<(NCELL/16 + 255)/256, 256>>>();
    k_prep   <<<NB, 64>>>(out, tgt);
    k_raster <<<NB*MAXT, 128>>>(out);
    k_noobj  <<<(NCELL/4 + 255)/256, 256>>>(out);
    k_matched<<<NB*MAXT, 96>>>(out);
    k_finish <<<1, 1>>>(res);
}